// round 3
// baseline (speedup 1.0000x reference)
#include <cuda_runtime.h>

#define NVERTS 2000000
#define NFACES 4000000
#define NITERS 10
#define DT 1e-8f
#define BULK 2500.0f
#define M21 ((1ull<<21)-1ull)
#define NBINS 8192

// Scratch (device globals: allocation-free per harness rules)
__device__ float4 g_x[NVERTS];                    // vertices, updated in place (32 MB)
__device__ unsigned long long g_fp[NFACES];       // packed 3x21-bit indices (unsorted)
__device__ unsigned long long g_fs[NFACES];       // packed indices, bucket-sorted by i0
__device__ unsigned int g_bins[NBINS];
__device__ unsigned int g_cur[NBINS];
__device__ double g_vol;
__device__ float g_p;
__device__ unsigned int g_cnt;

__device__ __forceinline__ void red4(float4* p, float x, float y, float z) {
    asm volatile("red.global.add.v4.f32 [%0], {%1, %2, %3, %4};"
                 :: "l"(p), "f"(x), "f"(y), "f"(z), "f"(0.0f) : "memory");
}

// ---------- prologue ----------

// Pack faces (auto int32/int64), seed x, zero counters.
__global__ void __launch_bounds__(256) k_init(const float* __restrict__ v,
                                              const void* __restrict__ fraw) {
    int i = blockIdx.x * 256 + threadIdx.x;

    const long long* f64 = (const long long*)fraw;
    const int* f32 = (const int*)fraw;
    bool is64 = true;
    #pragma unroll
    for (int k = 0; k < 8; k++)
        if ((unsigned long long)__ldg(&f64[k]) >= (unsigned long long)NVERTS) is64 = false;

    if (i < NFACES) {
        unsigned long long a, b, c;
        if (is64) {
            a = (unsigned long long)__ldg(&f64[3*i+0]);
            b = (unsigned long long)__ldg(&f64[3*i+1]);
            c = (unsigned long long)__ldg(&f64[3*i+2]);
        } else {
            a = (unsigned long long)(unsigned int)__ldg(&f32[3*i+0]);
            b = (unsigned long long)(unsigned int)__ldg(&f32[3*i+1]);
            c = (unsigned long long)(unsigned int)__ldg(&f32[3*i+2]);
        }
        g_fp[i] = a | (b << 21) | (c << 42);
    }
    if (i < NVERTS) g_x[i] = make_float4(v[3*i], v[3*i+1], v[3*i+2], 0.0f);
    if (i < NBINS) g_bins[i] = 0u;
    if (i == 0) { g_vol = 0.0; g_cnt = 0u; }
}

// Histogram of i0 >> 8 (buckets of 256 vertices).
__global__ void __launch_bounds__(256) k_hist() {
    __shared__ unsigned int h[NBINS];
    for (int k = threadIdx.x; k < NBINS; k += 256) h[k] = 0u;
    __syncthreads();
    int stride = gridDim.x * 256;
    for (int i = blockIdx.x * 256 + threadIdx.x; i < NFACES; i += stride) {
        unsigned int i0 = (unsigned int)(g_fp[i] & M21);
        atomicAdd(&h[i0 >> 8], 1u);
    }
    __syncthreads();
    for (int k = threadIdx.x; k < NBINS; k += 256)
        if (h[k]) atomicAdd(&g_bins[k], h[k]);
}

// Exclusive scan of 8192 bins (single block).
__global__ void __launch_bounds__(1024) k_scan() {
    __shared__ unsigned int w[32];
    int t = threadIdx.x;
    unsigned int loc[8], v = 0;
    #pragma unroll
    for (int k = 0; k < 8; k++) { loc[k] = g_bins[t*8+k]; v += loc[k]; }
    unsigned lane = t & 31, wid = t >> 5;
    unsigned s = v;
    #pragma unroll
    for (int o = 1; o < 32; o <<= 1) {
        unsigned n = __shfl_up_sync(0xffffffffu, s, o);
        if (lane >= o) s += n;
    }
    if (lane == 31) w[wid] = s;
    __syncthreads();
    if (wid == 0) {
        unsigned ws = w[lane];
        #pragma unroll
        for (int o = 1; o < 32; o <<= 1) {
            unsigned n = __shfl_up_sync(0xffffffffu, ws, o);
            if (lane >= o) ws += n;
        }
        w[lane] = ws;
    }
    __syncthreads();
    unsigned base = (wid ? w[wid-1] : 0u) + s - v;   // exclusive base for this chunk
    #pragma unroll
    for (int k = 0; k < 8; k++) { g_cur[t*8+k] = base; base += loc[k]; }
}

// Scatter into bucket order.
__global__ void __launch_bounds__(256) k_scatter() {
    int i = blockIdx.x * 256 + threadIdx.x;
    unsigned long long f = g_fp[i];
    unsigned int b = (unsigned int)(f & M21) >> 8;
    unsigned int pos = atomicAdd(&g_cur[b], 1u);
    g_fs[pos] = f;
}

// ---------- per-iteration ----------

// Pass 1: reduce vol over faces (2 faces/thread), last block computes p.
__global__ void __launch_bounds__(256) k_vol() {
    int i = blockIdx.x * 256 + threadIdx.x;            // pair index
    const float4* __restrict__ xs = g_x;
    float det = 0.0f;
    if (i < NFACES/2) {
        ulonglong2 fp = __ldg((const ulonglong2*)g_fs + i);
        int a0 = (int)(fp.x & M21), a1 = (int)((fp.x >> 21) & M21), a2 = (int)(fp.x >> 42);
        int b0 = (int)(fp.y & M21), b1 = (int)((fp.y >> 21) & M21), b2 = (int)(fp.y >> 42);
        float4 A0 = __ldg(&xs[a0]); float4 B0 = __ldg(&xs[b0]);
        float4 A1 = __ldg(&xs[a1]); float4 B1 = __ldg(&xs[b1]);
        float4 A2 = __ldg(&xs[a2]); float4 B2 = __ldg(&xs[b2]);
        det  = A0.x * (A1.y * A2.z - A1.z * A2.y)
             + A0.y * (A1.z * A2.x - A1.x * A2.z)
             + A0.z * (A1.x * A2.y - A1.y * A2.x);
        det += B0.x * (B1.y * B2.z - B1.z * B2.y)
             + B0.y * (B1.z * B2.x - B1.x * B2.z)
             + B0.z * (B1.x * B2.y - B1.y * B2.x);
    }
    #pragma unroll
    for (int o = 16; o > 0; o >>= 1) det += __shfl_down_sync(0xffffffffu, det, o);

    __shared__ float ws[8];
    if ((threadIdx.x & 31) == 0) ws[threadIdx.x >> 5] = det;
    __syncthreads();
    if (threadIdx.x == 0) {
        double s = 0.0;
        #pragma unroll
        for (int k = 0; k < 8; k++) s += (double)ws[k];
        atomicAdd(&g_vol, s);
        __threadfence();
        unsigned t = atomicInc(&g_cnt, gridDim.x - 1u);
        if (t == gridDim.x - 1u) {
            double vol = atomicAdd(&g_vol, 0.0) * (1.0 / 6.0);
            float stv = expf(0.04f);                   // exp(PRESSURE0/BULK)
            g_p = BULK * (stv - (float)vol) / stv;
            g_vol = 0.0;
        }
    }
}

// Pass 2: per-face forces, dt-scaled, atomically accumulated IN PLACE.
__global__ void __launch_bounds__(256) k_force() {
    int i = blockIdx.x * 256 + threadIdx.x;
    const float4* __restrict__ xs = g_x;

    unsigned long long f = __ldg(&g_fs[i]);
    int i0 = (int)(f & M21), i1 = (int)((f >> 21) & M21), i2 = (int)(f >> 42);
    float4 a = __ldg(&xs[i0]);
    float4 b = __ldg(&xs[i1]);
    float4 c = __ldg(&xs[i2]);

    float q = g_p * (DT / 6.0f);     // dt * p * (cross/6)
    const float s = 0.5f * DT;       // dt * SURFACE_TENSION * 0.5

    float e1x = b.x - a.x, e1y = b.y - a.y, e1z = b.z - a.z;
    float e2x = c.x - a.x, e2y = c.y - a.y, e2z = c.z - a.z;
    float nx = e1y * e2z - e1z * e2y;
    float ny = e1z * e2x - e1x * e2z;
    float nz = e1x * e2y - e1y * e2x;
    float inv = 1.0f / (sqrtf(nx*nx + ny*ny + nz*nz) + 1e-12f);
    float hx = nx * inv, hy = ny * inv, hz = nz * inv;

    float d0x = c.x - b.x, d0y = c.y - b.y, d0z = c.z - b.z;
    float g0x = q * (b.y*c.z - b.z*c.y) - s * (hy*d0z - hz*d0y);
    float g0y = q * (b.z*c.x - b.x*c.z) - s * (hz*d0x - hx*d0z);
    float g0z = q * (b.x*c.y - b.y*c.x) - s * (hx*d0y - hy*d0x);
    float d1x = a.x - c.x, d1y = a.y - c.y, d1z = a.z - c.z;
    float g1x = q * (c.y*a.z - c.z*a.y) - s * (hy*d1z - hz*d1y);
    float g1y = q * (c.z*a.x - c.x*a.z) - s * (hz*d1x - hx*d1z);
    float g1z = q * (c.x*a.y - c.y*a.x) - s * (hx*d1y - hy*d1x);
    float g2x = q * (a.y*b.z - a.z*b.y) - s * (hy*e1z - hz*e1y);
    float g2y = q * (a.z*b.x - a.x*b.z) - s * (hz*e1x - hx*e1z);
    float g2z = q * (a.x*b.y - a.y*b.x) - s * (hx*e1y - hy*e1x);

    red4(&g_x[i0], g0x, g0y, g0z);
    red4(&g_x[i1], g1x, g1y, g1z);
    red4(&g_x[i2], g2x, g2y, g2z);
}

// Final: unpad into d_out.
__global__ void __launch_bounds__(256) k_pack(float* __restrict__ out) {
    int i = blockIdx.x * 256 + threadIdx.x;
    if (i < NVERTS) {
        float4 v = g_x[i];
        out[3*i] = v.x; out[3*i+1] = v.y; out[3*i+2] = v.z;
    }
}

extern "C" void kernel_launch(void* const* d_in, const int* in_sizes, int n_in,
                              void* d_out, int out_size) {
    const float* verts;
    const void* faces;
    if (in_sizes[0] == 3 * NVERTS) { verts = (const float*)d_in[0]; faces = d_in[1]; }
    else                           { verts = (const float*)d_in[1]; faces = d_in[0]; }

    const int FB = NFACES / 256;                    // 15625, exact cover
    const int VB = (NFACES/2 + 255) / 256;          // vol: 2 faces/thread

    k_init<<<FB, 256>>>(verts, faces);
    k_hist<<<1184, 256>>>();
    k_scan<<<1, 1024>>>();
    k_scatter<<<FB, 256>>>();
    for (int it = 0; it < NITERS; it++) {
        k_vol<<<VB, 256>>>();
        k_force<<<FB, 256>>>();
    }
    k_pack<<<(NVERTS + 255) / 256, 256>>>((float*)d_out);
}